// round 3
// baseline (speedup 1.0000x reference)
#include <cuda_runtime.h>

#define C_MLP 32
#define NV    10              // v = (x,y,z,f0..4,cx,cy)
#define NPAIR 55              // upper triangle of 10x10
#define NSTAT 65              // 55 + 10
#define GRID_A 1184
#define BLK_A  256
#define PSIZE  0.075f
#define XMIN  -54.0f
#define YMIN  -54.0f
#define CZ    -1.0f           // 0.5*(Z_MIN+Z_MAX)
#define BN_EPS 1e-3f
#define MMAX   131072
#define CAP    64

// static scratch
__device__ float  g_part[GRID_A * 72];     // per-block partial stats
__device__ float4 g_A4[NV * 8];            // folded weights A' (10 x 32)
__device__ float  g_e[C_MLP];              // folded bias e
__device__ int    g_cnt[MMAX];
__device__ int    g_slot[MMAX * CAP];

// ---------------------------------------------------------------------------
__global__ void zero_cnt_kernel(int M) {
    int i = blockIdx.x * blockDim.x + threadIdx.x;
    if (i < M) g_cnt[i] = 0;
}

// ---------------------------------------------------------------------------
// Scatter: bucketed inverse index (counting sort without scan)
// ---------------------------------------------------------------------------
__global__ void scatter_kernel(const int* __restrict__ psi, int N) {
    int i = blockIdx.x * blockDim.x + threadIdx.x;
    if (i >= N) return;
    int p = psi[i];
    int pos = atomicAdd(&g_cnt[p], 1);
    if (pos < CAP) g_slot[p * CAP + pos] = i;
}

// ---------------------------------------------------------------------------
// Stage A: accumulate sums and second moments of v (10 vars):
// v = (x, y, z, f0..f4, cx, cy)
// ---------------------------------------------------------------------------
__global__ __launch_bounds__(BLK_A)
void stageA_kernel(const float* __restrict__ xyz,
                   const float* __restrict__ ptf,
                   const int*   __restrict__ pil,
                   const int*   __restrict__ psi,
                   int N)
{
    float acc[NPAIR];
    float s[NV];
#pragma unroll
    for (int j = 0; j < NPAIR; j++) acc[j] = 0.f;
#pragma unroll
    for (int j = 0; j < NV; j++) s[j] = 0.f;

    const int stride = GRID_A * BLK_A;
    for (int i = blockIdx.x * BLK_A + threadIdx.x; i < N; i += stride) {
        int p  = psi[i];
        int py = pil[3 * p + 1];
        int px = pil[3 * p + 2];
        float v[NV];
        v[0] = xyz[3 * i + 0];
        v[1] = xyz[3 * i + 1];
        v[2] = xyz[3 * i + 2];
#pragma unroll
        for (int k = 0; k < 5; k++) v[3 + k] = ptf[5 * i + k];
        v[8] = ((float)px + 0.5f) * PSIZE + XMIN;
        v[9] = ((float)py + 0.5f) * PSIZE + YMIN;

        int j = 0;
#pragma unroll
        for (int a = 0; a < NV; a++) {
            s[a] += v[a];
#pragma unroll
            for (int b = a; b < NV; b++) {
                acc[j] = fmaf(v[a], v[b], acc[j]);
                j++;
            }
        }
    }

#pragma unroll
    for (int j = 0; j < NPAIR; j++) {
        float t = acc[j];
        t += __shfl_xor_sync(0xffffffffu, t, 16);
        t += __shfl_xor_sync(0xffffffffu, t, 8);
        t += __shfl_xor_sync(0xffffffffu, t, 4);
        t += __shfl_xor_sync(0xffffffffu, t, 2);
        t += __shfl_xor_sync(0xffffffffu, t, 1);
        acc[j] = t;
    }
#pragma unroll
    for (int j = 0; j < NV; j++) {
        float t = s[j];
        t += __shfl_xor_sync(0xffffffffu, t, 16);
        t += __shfl_xor_sync(0xffffffffu, t, 8);
        t += __shfl_xor_sync(0xffffffffu, t, 4);
        t += __shfl_xor_sync(0xffffffffu, t, 2);
        t += __shfl_xor_sync(0xffffffffu, t, 1);
        s[j] = t;
    }

    __shared__ float sm[BLK_A / 32][NSTAT];
    int lane = threadIdx.x & 31;
    int wid  = threadIdx.x >> 5;
    if (lane == 0) {
#pragma unroll
        for (int j = 0; j < NPAIR; j++) sm[wid][j] = acc[j];
#pragma unroll
        for (int j = 0; j < NV; j++) sm[wid][NPAIR + j] = s[j];
    }
    __syncthreads();
    if (threadIdx.x < NSTAT) {
        float t = 0.f;
#pragma unroll
        for (int w = 0; w < BLK_A / 32; w++) t += sm[w][threadIdx.x];
        g_part[blockIdx.x * 72 + threadIdx.x] = t;
    }
}

// ---------------------------------------------------------------------------
// Stage B: reduce partials; build folded weights.
//   h_c = v . a_c + b_c  with a derived from W, b_c = -CZ * W[2][c]
//   y   = sc*(h - mean) + beta = v . (sc*a) + (beta - sc*mva),  mva = E[v].a
// Writes A' (10x32) and e (32).
// ---------------------------------------------------------------------------
__global__ void stageB_kernel(const float* __restrict__ W,
                              const float* __restrict__ gamma,
                              const float* __restrict__ beta,
                              int N)
{
    __shared__ float red[NSTAT];
    int t = threadIdx.x;           // 96 threads
    if (t < NSTAT) {
        float a0 = 0.f, a1 = 0.f, a2 = 0.f, a3 = 0.f;
        int b = 0;
        for (; b + 4 <= GRID_A; b += 4) {
            a0 += g_part[(b + 0) * 72 + t];
            a1 += g_part[(b + 1) * 72 + t];
            a2 += g_part[(b + 2) * 72 + t];
            a3 += g_part[(b + 3) * 72 + t];
        }
        for (; b < GRID_A; b++) a0 += g_part[b * 72 + t];
        red[t] = (a0 + a1) + (a2 + a3);
    }
    __syncthreads();
    if (t < C_MLP) {
        float w[11];
#pragma unroll
        for (int k = 0; k < 11; k++) w[k] = W[k * C_MLP + t];
        float a[NV];
        a[0] = w[0] + w[3];
        a[1] = w[1] + w[4];
        a[2] = w[2] + w[5];
#pragma unroll
        for (int k = 0; k < 5; k++) a[3 + k] = w[6 + k];
        a[8] = -w[0];
        a[9] = -w[1];
        float bb = -CZ * w[2];

        const float invN = 1.0f / (float)N;
        float mva = 0.f;
#pragma unroll
        for (int k = 0; k < NV; k++) mva = fmaf(a[k], red[NPAIR + k] * invN, mva);

        float quad = 0.f;
        int j = 0;
#pragma unroll
        for (int p = 0; p < NV; p++) {
            quad = fmaf(a[p] * a[p], red[j], quad);  j++;
#pragma unroll
            for (int q = p + 1; q < NV; q++) {
                quad = fmaf(2.f * a[p] * a[q], red[j], quad);  j++;
            }
        }
        quad *= invN;

        float mean = mva + bb;
        float ex2  = quad + 2.f * bb * mva + bb * bb;
        float var  = ex2 - mean * mean;
        float sc   = gamma[t] * rsqrtf(var + BN_EPS);

        float* A = (float*)g_A4;
#pragma unroll
        for (int k = 0; k < NV; k++) A[k * C_MLP + t] = sc * a[k];
        g_e[t] = beta[t] - sc * mva;
    }
}

// ---------------------------------------------------------------------------
// Pool: warp-uniform channel quad. Warp w handles quad q = w&3 for 32
// consecutive pillars (lane = pillar). All LDS are warp-broadcast.
// Per pillar precompute d = cx*A'[8] + cy*A'[9] + e once; inner loop is
// 8 k-iters of 2 LDS.128 + 8 FMA per point.
// ---------------------------------------------------------------------------
__global__ __launch_bounds__(256)
void pool_kernel(const float* __restrict__ xyz,
                 const float* __restrict__ ptf,
                 const int*   __restrict__ pil,
                 float* __restrict__ out,
                 int M)
{
    __shared__ float4 As4[NV * 8];
    __shared__ float  es[C_MLP];
    if (threadIdx.x < NV * 8) As4[threadIdx.x] = g_A4[threadIdx.x];
    if (threadIdx.x >= 96 && threadIdx.x < 128) es[threadIdx.x - 96] = g_e[threadIdx.x - 96];
    __syncthreads();

    int w    = threadIdx.x >> 5;
    int lane = threadIdx.x & 31;
    int q    = w & 3;                                   // uniform per warp
    int p    = blockIdx.x * 64 + (w >> 2) * 32 + lane;  // pillar
    if (p >= M) return;

    int cnt = g_cnt[p];
    if (cnt > CAP) cnt = CAP;

    float cx = ((float)pil[3 * p + 2] + 0.5f) * PSIZE + XMIN;
    float cy = ((float)pil[3 * p + 1] + 0.5f) * PSIZE + YMIN;

    // per-pillar constant d = cx*A'[8] + cy*A'[9] + e
    float d[8];
    {
        float4 a8a = As4[8 * 8 + q * 2], a8b = As4[8 * 8 + q * 2 + 1];
        float4 a9a = As4[9 * 8 + q * 2], a9b = As4[9 * 8 + q * 2 + 1];
        d[0] = fmaf(cx, a8a.x, fmaf(cy, a9a.x, es[q * 8 + 0]));
        d[1] = fmaf(cx, a8a.y, fmaf(cy, a9a.y, es[q * 8 + 1]));
        d[2] = fmaf(cx, a8a.z, fmaf(cy, a9a.z, es[q * 8 + 2]));
        d[3] = fmaf(cx, a8a.w, fmaf(cy, a9a.w, es[q * 8 + 3]));
        d[4] = fmaf(cx, a8b.x, fmaf(cy, a9b.x, es[q * 8 + 4]));
        d[5] = fmaf(cx, a8b.y, fmaf(cy, a9b.y, es[q * 8 + 5]));
        d[6] = fmaf(cx, a8b.z, fmaf(cy, a9b.z, es[q * 8 + 6]));
        d[7] = fmaf(cx, a8b.w, fmaf(cy, a9b.w, es[q * 8 + 7]));
    }

    float m[8];
#pragma unroll
    for (int u = 0; u < 8; u++) m[u] = 0.f;

    const int* sl = g_slot + (size_t)p * CAP;
#pragma unroll 2
    for (int j = 0; j < cnt; j++) {
        int i = sl[j];
        float v[8];
        v[0] = __ldg(&xyz[3 * i + 0]);
        v[1] = __ldg(&xyz[3 * i + 1]);
        v[2] = __ldg(&xyz[3 * i + 2]);
#pragma unroll
        for (int k = 0; k < 5; k++) v[3 + k] = __ldg(&ptf[5 * i + k]);

        float hv[8];
#pragma unroll
        for (int u = 0; u < 8; u++) hv[u] = d[u];
#pragma unroll
        for (int k = 0; k < 8; k++) {
            float gk = v[k];
            float4 wA = As4[k * 8 + q * 2];
            float4 wB = As4[k * 8 + q * 2 + 1];
            hv[0] = fmaf(gk, wA.x, hv[0]);
            hv[1] = fmaf(gk, wA.y, hv[1]);
            hv[2] = fmaf(gk, wA.z, hv[2]);
            hv[3] = fmaf(gk, wA.w, hv[3]);
            hv[4] = fmaf(gk, wB.x, hv[4]);
            hv[5] = fmaf(gk, wB.y, hv[5]);
            hv[6] = fmaf(gk, wB.z, hv[6]);
            hv[7] = fmaf(gk, wB.w, hv[7]);
        }
#pragma unroll
        for (int u = 0; u < 8; u++) m[u] = fmaxf(m[u], hv[u]);
    }

    float4* o = (float4*)(out + (size_t)p * C_MLP + q * 8);
    o[0] = make_float4(m[0], m[1], m[2], m[3]);
    o[1] = make_float4(m[4], m[5], m[6], m[7]);
}

// ---------------------------------------------------------------------------
extern "C" void kernel_launch(void* const* d_in, const int* in_sizes, int n_in,
                              void* d_out, int out_size)
{
    const float* xyz   = (const float*)d_in[0];   // (N,3)
    const float* ptf   = (const float*)d_in[1];   // (N,5)
    const float* W1    = (const float*)d_in[2];   // (11,32)
    const float* gamma = (const float*)d_in[3];   // (32)
    const float* beta  = (const float*)d_in[4];   // (32)
    const int*   pil   = (const int*)d_in[5];     // (M,3)
    const int*   psi   = (const int*)d_in[6];     // (N)
    int N = in_sizes[6];
    int M = in_sizes[5] / 3;
    float* out = (float*)d_out;                   // (M,32)

    zero_cnt_kernel<<<(M + 255) / 256, 256>>>(M);
    scatter_kernel<<<(N + 255) / 256, 256>>>(psi, N);
    stageA_kernel<<<GRID_A, BLK_A>>>(xyz, ptf, pil, psi, N);
    stageB_kernel<<<1, 96>>>(W1, gamma, beta, N);
    pool_kernel<<<(M + 63) / 64, 256>>>(xyz, ptf, pil, out, M);
}

// round 4
// speedup vs baseline: 1.3356x; 1.3356x over previous
#include <cuda_runtime.h>

#define C_MLP 32
#define NV    10              // v = (x,y,z,f0..4,cx,cy)
#define NPAIR 55              // upper triangle of 10x10
#define NSTAT 65              // 55 + 10
#define GRID_A 296
#define BLK_A  256
#define PSIZE  0.075f
#define XMIN  -54.0f
#define YMIN  -54.0f
#define CZ    -1.0f
#define BN_EPS 1e-3f
#define MMAX   131072
#define CAP    64

// static scratch
__device__ float  g_part[GRID_A * 72];       // per-block partial stats
__device__ float4 g_A4[NV * 8];              // folded weights A' (10 x 32)
__device__ float  g_e[C_MLP];                // folded bias
__device__ int    g_cnt[MMAX];
__device__ float4 g_pay[(size_t)MMAX * CAP * 2];  // bucketed point payloads (32B each)

// ---------------------------------------------------------------------------
__global__ void zero_cnt_kernel(int M) {
    int i = blockIdx.x * blockDim.x + threadIdx.x;
    if (i < M) g_cnt[i] = 0;
}

// ---------------------------------------------------------------------------
// Stage A (fused): per point — gather pillar center, accumulate 10-var
// sums + second moments, and scatter the point payload into its pillar's
// bucket (two STG.128). One coalesced read pass over all point data.
// ---------------------------------------------------------------------------
__global__ __launch_bounds__(BLK_A)
void stageA_kernel(const float* __restrict__ xyz,
                   const float* __restrict__ ptf,
                   const int*   __restrict__ pil,
                   const int*   __restrict__ psi,
                   int N)
{
    float acc[NPAIR];
    float s[NV];
#pragma unroll
    for (int j = 0; j < NPAIR; j++) acc[j] = 0.f;
#pragma unroll
    for (int j = 0; j < NV; j++) s[j] = 0.f;

    const int stride = GRID_A * BLK_A;
    for (int i = blockIdx.x * BLK_A + threadIdx.x; i < N; i += stride) {
        int p  = psi[i];
        int py = pil[3 * p + 1];
        int px = pil[3 * p + 2];
        float v[NV];
        v[0] = xyz[3 * i + 0];
        v[1] = xyz[3 * i + 1];
        v[2] = xyz[3 * i + 2];
#pragma unroll
        for (int k = 0; k < 5; k++) v[3 + k] = ptf[5 * i + k];
        v[8] = ((float)px + 0.5f) * PSIZE + XMIN;
        v[9] = ((float)py + 0.5f) * PSIZE + YMIN;

        // bucket scatter of the payload
        int pos = atomicAdd(&g_cnt[p], 1);
        if (pos < CAP) {
            size_t base = ((size_t)p * CAP + pos) * 2;
            g_pay[base]     = make_float4(v[0], v[1], v[2], v[3]);
            g_pay[base + 1] = make_float4(v[4], v[5], v[6], v[7]);
        }

        int j = 0;
#pragma unroll
        for (int a = 0; a < NV; a++) {
            s[a] += v[a];
#pragma unroll
            for (int b = a; b < NV; b++) {
                acc[j] = fmaf(v[a], v[b], acc[j]);
                j++;
            }
        }
    }

#pragma unroll
    for (int j = 0; j < NPAIR; j++) {
        float t = acc[j];
        t += __shfl_xor_sync(0xffffffffu, t, 16);
        t += __shfl_xor_sync(0xffffffffu, t, 8);
        t += __shfl_xor_sync(0xffffffffu, t, 4);
        t += __shfl_xor_sync(0xffffffffu, t, 2);
        t += __shfl_xor_sync(0xffffffffu, t, 1);
        acc[j] = t;
    }
#pragma unroll
    for (int j = 0; j < NV; j++) {
        float t = s[j];
        t += __shfl_xor_sync(0xffffffffu, t, 16);
        t += __shfl_xor_sync(0xffffffffu, t, 8);
        t += __shfl_xor_sync(0xffffffffu, t, 4);
        t += __shfl_xor_sync(0xffffffffu, t, 2);
        t += __shfl_xor_sync(0xffffffffu, t, 1);
        s[j] = t;
    }

    __shared__ float sm[BLK_A / 32][NSTAT];
    int lane = threadIdx.x & 31;
    int wid  = threadIdx.x >> 5;
    if (lane == 0) {
#pragma unroll
        for (int j = 0; j < NPAIR; j++) sm[wid][j] = acc[j];
#pragma unroll
        for (int j = 0; j < NV; j++) sm[wid][NPAIR + j] = s[j];
    }
    __syncthreads();
    if (threadIdx.x < NSTAT) {
        float t = 0.f;
#pragma unroll
        for (int w = 0; w < BLK_A / 32; w++) t += sm[w][threadIdx.x];
        g_part[blockIdx.x * 72 + threadIdx.x] = t;
    }
}

// ---------------------------------------------------------------------------
// Stage B: reduce partials; fold BN into weights.
//   h_c = v.a_c + b_c,  a from W (center-diff fold), b_c = -CZ*W[2][c]
//   y   = v.(sc*a) + (beta - sc*mva)
// ---------------------------------------------------------------------------
__global__ void stageB_kernel(const float* __restrict__ W,
                              const float* __restrict__ gamma,
                              const float* __restrict__ beta,
                              int N)
{
    __shared__ float red[NSTAT];
    int t = threadIdx.x;           // 96 threads
    if (t < NSTAT) {
        float a0 = 0.f, a1 = 0.f, a2 = 0.f, a3 = 0.f;
        int b = 0;
        for (; b + 4 <= GRID_A; b += 4) {
            a0 += g_part[(b + 0) * 72 + t];
            a1 += g_part[(b + 1) * 72 + t];
            a2 += g_part[(b + 2) * 72 + t];
            a3 += g_part[(b + 3) * 72 + t];
        }
        for (; b < GRID_A; b++) a0 += g_part[b * 72 + t];
        red[t] = (a0 + a1) + (a2 + a3);
    }
    __syncthreads();
    if (t < C_MLP) {
        float w[11];
#pragma unroll
        for (int k = 0; k < 11; k++) w[k] = W[k * C_MLP + t];
        float a[NV];
        a[0] = w[0] + w[3];
        a[1] = w[1] + w[4];
        a[2] = w[2] + w[5];
#pragma unroll
        for (int k = 0; k < 5; k++) a[3 + k] = w[6 + k];
        a[8] = -w[0];
        a[9] = -w[1];
        float bb = -CZ * w[2];

        const float invN = 1.0f / (float)N;
        float mva = 0.f;
#pragma unroll
        for (int k = 0; k < NV; k++) mva = fmaf(a[k], red[NPAIR + k] * invN, mva);

        float quad = 0.f;
        int j = 0;
#pragma unroll
        for (int p = 0; p < NV; p++) {
            quad = fmaf(a[p] * a[p], red[j], quad);  j++;
#pragma unroll
            for (int q = p + 1; q < NV; q++) {
                quad = fmaf(2.f * a[p] * a[q], red[j], quad);  j++;
            }
        }
        quad *= invN;

        float mean = mva + bb;
        float ex2  = quad + 2.f * bb * mva + bb * bb;
        float var  = ex2 - mean * mean;
        float sc   = gamma[t] * rsqrtf(var + BN_EPS);

        float* A = (float*)g_A4;
#pragma unroll
        for (int k = 0; k < NV; k++) A[k * C_MLP + t] = sc * a[k];
        g_e[t] = beta[t] - sc * mva;
    }
}

// ---------------------------------------------------------------------------
// Pool: one lane = one pillar, all 32 channels in registers. Payload gather
// is 2x LDG.128 per point from the pillar's contiguous bucket. Weight LDS
// are warp-broadcast (k uniform across lanes).
// ---------------------------------------------------------------------------
__global__ __launch_bounds__(256)
void pool_kernel(const int* __restrict__ pil,
                 float* __restrict__ out,
                 int M)
{
    __shared__ float4 As4[NV * 8];
    __shared__ float  es[C_MLP];
    if (threadIdx.x < NV * 8) As4[threadIdx.x] = g_A4[threadIdx.x];
    if (threadIdx.x >= 96 && threadIdx.x < 128) es[threadIdx.x - 96] = g_e[threadIdx.x - 96];
    __syncthreads();

    int p = blockIdx.x * blockDim.x + threadIdx.x;
    if (p >= M) return;

    int cnt = g_cnt[p];
    if (cnt > CAP) cnt = CAP;

    float cx = ((float)pil[3 * p + 2] + 0.5f) * PSIZE + XMIN;
    float cy = ((float)pil[3 * p + 1] + 0.5f) * PSIZE + YMIN;

    // per-pillar constant d = cx*A'[8] + cy*A'[9] + e
    float d[C_MLP];
#pragma unroll
    for (int q = 0; q < 8; q++) {
        float4 a8 = As4[8 * 8 + q];
        float4 a9 = As4[9 * 8 + q];
        d[4 * q + 0] = fmaf(cx, a8.x, fmaf(cy, a9.x, es[4 * q + 0]));
        d[4 * q + 1] = fmaf(cx, a8.y, fmaf(cy, a9.y, es[4 * q + 1]));
        d[4 * q + 2] = fmaf(cx, a8.z, fmaf(cy, a9.z, es[4 * q + 2]));
        d[4 * q + 3] = fmaf(cx, a8.w, fmaf(cy, a9.w, es[4 * q + 3]));
    }

    float m[C_MLP];
#pragma unroll
    for (int u = 0; u < C_MLP; u++) m[u] = 0.f;

    const float4* pay = g_pay + (size_t)p * CAP * 2;
    for (int j = 0; j < cnt; j++) {
        float4 va = __ldg(&pay[2 * j]);
        float4 vb = __ldg(&pay[2 * j + 1]);
        float v[8] = {va.x, va.y, va.z, va.w, vb.x, vb.y, vb.z, vb.w};

        float hv[C_MLP];
#pragma unroll
        for (int u = 0; u < C_MLP; u++) hv[u] = d[u];
#pragma unroll
        for (int k = 0; k < 8; k++) {
            float gk = v[k];
#pragma unroll
            for (int q = 0; q < 8; q++) {
                float4 w = As4[k * 8 + q];
                hv[4 * q + 0] = fmaf(gk, w.x, hv[4 * q + 0]);
                hv[4 * q + 1] = fmaf(gk, w.y, hv[4 * q + 1]);
                hv[4 * q + 2] = fmaf(gk, w.z, hv[4 * q + 2]);
                hv[4 * q + 3] = fmaf(gk, w.w, hv[4 * q + 3]);
            }
        }
#pragma unroll
        for (int u = 0; u < C_MLP; u++) m[u] = fmaxf(m[u], hv[u]);
    }

    float4* o = (float4*)(out + (size_t)p * C_MLP);
#pragma unroll
    for (int q = 0; q < 8; q++)
        o[q] = make_float4(m[4 * q + 0], m[4 * q + 1], m[4 * q + 2], m[4 * q + 3]);
}

// ---------------------------------------------------------------------------
extern "C" void kernel_launch(void* const* d_in, const int* in_sizes, int n_in,
                              void* d_out, int out_size)
{
    const float* xyz   = (const float*)d_in[0];   // (N,3)
    const float* ptf   = (const float*)d_in[1];   // (N,5)
    const float* W1    = (const float*)d_in[2];   // (11,32)
    const float* gamma = (const float*)d_in[3];   // (32)
    const float* beta  = (const float*)d_in[4];   // (32)
    const int*   pil   = (const int*)d_in[5];     // (M,3)
    const int*   psi   = (const int*)d_in[6];     // (N)
    int N = in_sizes[6];
    int M = in_sizes[5] / 3;
    float* out = (float*)d_out;                   // (M,32)

    zero_cnt_kernel<<<(M + 255) / 256, 256>>>(M);
    stageA_kernel<<<GRID_A, BLK_A>>>(xyz, ptf, pil, psi, N);
    stageB_kernel<<<1, 96>>>(W1, gamma, beta, N);
    pool_kernel<<<(M + 255) / 256, 256>>>(pil, out, M);
}